// round 7
// baseline (speedup 1.0000x reference)
#include <cuda_runtime.h>

// FixedFoveatedSensor: out[b,c,h,w] = sum_s bilinear(img, warp(pos_s)) * det_s / sum_s det_s
// img: (4,3,1024,1024) f32, t: (1,) f32, jitter: (16,256,256,2) f32, out: (4,3,256,256) f32
//
// 6 thread-groups per pixel, each handling 2 of the 12 (b,c) planes.
// 393216 threads (~83 warps/SM demand) to push L1tex to its throughput ceiling.
// Coordinates/det recomputed per group (fma/alu pipes have headroom).
// Zero cross-thread communication, no early returns.

#define SPP 16
#define SH 256
#define SW 256
#define NBC 12
#define CH_PER_GROUP 2
#define NGROUPS 6
#define IMG_H 1024
#define IMG_W 1024

__global__ __launch_bounds__(128)
void ffs_kernel(const float* __restrict__ img,
                const float* __restrict__ t,
                const float* __restrict__ jitter,
                float* __restrict__ out)
{
    const int tid   = blockIdx.x * blockDim.x + threadIdx.x;
    const int pixel = tid & (SH * SW - 1);      // fast dim: adjacent lanes = adjacent pixels
    const int grp   = tid >> 16;                // 0..5, which 2-channel group
    const int h = pixel >> 8;
    const int w = pixel & 255;

    const float tt    = t[0];
    const float s_inv = 1.0f / tanhf(tt);
    const float step  = 2.0f / 256.0f;
    const float base_x = -1.0f + (float)w * step;
    const float base_y = -1.0f + (float)h * step;

    const float* __restrict__ plane0 = img + (size_t)(grp * CH_PER_GROUP) * (IMG_H * IMG_W);
    const float* __restrict__ plane1 = plane0 + (IMG_H * IMG_W);

    float acc0 = 0.0f, acc1 = 0.0f;
    float accDet = 0.0f;

#pragma unroll 4
    for (int s = 0; s < SPP; s++) {
        const float2 jit = *(const float2*)(jitter + (((size_t)s * SH + h) * SW + w) * 2);
        const float posx = fmaf(jit.x, step, base_x);
        const float posy = fmaf(jit.y, step, base_y);

        const float thx = tanhf(tt * posx);
        const float thy = tanhf(tt * posy);
        const float wrx = thx * s_inv;
        const float wry = thy * s_inv;
        const float ddx = tt * (1.0f - thx * thx) * s_inv;
        const float ddy = tt * (1.0f - thy * thy) * s_inv;
        const float det = ddx * ddy;
        accDet += det;

        float gx = (wrx + 1.0f) * (0.5f * IMG_W) - 0.5f;
        float gy = (wry + 1.0f) * (0.5f * IMG_H) - 0.5f;
        gx = fminf(fmaxf(gx, 0.0f), (float)(IMG_W - 1));
        gy = fminf(fmaxf(gy, 0.0f), (float)(IMG_H - 1));
        const float x0f = floorf(gx);
        const float y0f = floorf(gy);
        const float fx = gx - x0f;
        const float fy = gy - y0f;
        const int x0 = (int)x0f;
        const int y0 = (int)y0f;
        const int x1 = min(x0 + 1, IMG_W - 1);
        const int y1 = min(y0 + 1, IMG_H - 1);

        // fold det into bilinear weights
        const float w11 = fx * fy * det;
        const float w01 = fx * det - w11;
        const float w10 = fy * det - w11;
        const float w00 = det - w01 - w10 - w11;

        const int i00 = y0 * IMG_W + x0;
        const int i01 = y0 * IMG_W + x1;
        const int i10 = y1 * IMG_W + x0;
        const int i11 = y1 * IMG_W + x1;

        {
            float v = plane0[i00] * w00;
            v = fmaf(plane0[i01], w01, v);
            v = fmaf(plane0[i10], w10, v);
            v = fmaf(plane0[i11], w11, v);
            acc0 += v;
        }
        {
            float v = plane1[i00] * w00;
            v = fmaf(plane1[i01], w01, v);
            v = fmaf(plane1[i10], w10, v);
            v = fmaf(plane1[i11], w11, v);
            acc1 += v;
        }
    }

    const float inv = 1.0f / accDet;
    float* __restrict__ o = out + (size_t)(grp * CH_PER_GROUP) * (SH * SW) + pixel;
    o[0]       = acc0 * inv;
    o[SH * SW] = acc1 * inv;
}

extern "C" void kernel_launch(void* const* d_in, const int* in_sizes, int n_in,
                              void* d_out, int out_size)
{
    const float* img    = (const float*)d_in[0];
    const float* t      = (const float*)d_in[1];
    const float* jitter = (const float*)d_in[2];
    float* out          = (float*)d_out;

    ffs_kernel<<<(SH * SW * NGROUPS) / 128, 128>>>(img, t, jitter, out);
}

// round 8
// speedup vs baseline: 1.0548x; 1.0548x over previous
#include <cuda_runtime.h>

// FixedFoveatedSensor: out[b,c,h,w] = sum_s bilinear(img, warp(pos_s)) * det_s / sum_s det_s
// img: (4,3,1024,1024) f32, t: (1,) f32, jitter: (16,256,256,2) f32, out: (4,3,256,256) f32
//
// spp-major lane layout: warp = 2 adjacent pixels x 16 spp (one spp per lane, all 12
// channels per lane). All 32 lanes of a warp sample within a ~3-sensor-pixel footprint,
// cutting L1 gather wavefronts ~3x vs the pixel-major layout. 16-spp reduction done via
// shared memory with full-block __syncthreads (no shuffles, no divergence hazards).

#define SPP 16
#define SH 256
#define SW 256
#define NBC 12
#define NVALS 13            // 12 channel accums + det
#define PIX_PER_BLOCK 8
#define BLOCK 128           // 8 pixels * 16 spp
#define IMG_H 1024
#define IMG_W 1024

__global__ __launch_bounds__(BLOCK)
void ffs_kernel(const float* __restrict__ img,
                const float* __restrict__ t,
                const float* __restrict__ jitter,
                float* __restrict__ out)
{
    __shared__ float red[BLOCK * NVALS];     // 6656 B
    __shared__ float det_s[PIX_PER_BLOCK];

    const int tid  = threadIdx.x;
    const int spp  = tid & 15;               // lane fast dim: spp
    const int pin  = tid >> 4;               // pixel within block: 0..7
    const int pixel = blockIdx.x * PIX_PER_BLOCK + pin;
    const int h = pixel >> 8;
    const int w = pixel & 255;

    const float tt    = t[0];
    const float s_inv = 1.0f / tanhf(tt);
    const float step  = 2.0f / 256.0f;

    // per-lane sample position (one spp per lane)
    const float2 jit = ((const float2*)jitter)[((size_t)spp * SH + h) * SW + w];
    const float posx = fmaf(jit.x, step, -1.0f + (float)w * step);
    const float posy = fmaf(jit.y, step, -1.0f + (float)h * step);

    const float thx = tanhf(tt * posx);
    const float thy = tanhf(tt * posy);
    const float wrx = thx * s_inv;
    const float wry = thy * s_inv;
    const float ddx = tt * (1.0f - thx * thx) * s_inv;
    const float ddy = tt * (1.0f - thy * thy) * s_inv;
    const float det = ddx * ddy;

    float gx = (wrx + 1.0f) * (0.5f * IMG_W) - 0.5f;
    float gy = (wry + 1.0f) * (0.5f * IMG_H) - 0.5f;
    gx = fminf(fmaxf(gx, 0.0f), (float)(IMG_W - 1));
    gy = fminf(fmaxf(gy, 0.0f), (float)(IMG_H - 1));
    const float x0f = floorf(gx);
    const float y0f = floorf(gy);
    const float fx = gx - x0f;
    const float fy = gy - y0f;
    const int x0 = (int)x0f;
    const int y0 = (int)y0f;
    const int x1 = min(x0 + 1, IMG_W - 1);
    const int y1 = min(y0 + 1, IMG_H - 1);

    // fold det into bilinear weights
    const float w11 = fx * fy * det;
    const float w01 = fx * det - w11;
    const float w10 = fy * det - w11;
    const float w00 = det - w01 - w10 - w11;

    const int i00 = y0 * IMG_W + x0;
    const int i01 = y0 * IMG_W + x1;
    const int i10 = y1 * IMG_W + x0;
    const int i11 = y1 * IMG_W + x1;

    // gather all 12 channels for this lane's single sample (48 independent LDGs)
    float acc[NBC];
#pragma unroll
    for (int bc = 0; bc < NBC; bc++) {
        const float* __restrict__ p = img + (size_t)bc * (IMG_H * IMG_W);
        float v = p[i00] * w00;
        v = fmaf(p[i01], w01, v);
        v = fmaf(p[i10], w10, v);
        v = fmaf(p[i11], w11, v);
        acc[bc] = v;
    }

    // stage per-lane partials: 13 floats per thread (stride 13, coprime with 32 banks)
#pragma unroll
    for (int j = 0; j < NBC; j++) red[tid * NVALS + j] = acc[j];
    red[tid * NVALS + NBC] = det;
    __syncthreads();

    // 104 sums needed: 8 pixels x 13 values; each summing thread adds its 16 spp lanes
    float sum = 0.0f;
    int p = 0, j = 0;
    if (tid < PIX_PER_BLOCK * NVALS) {
        p = tid / NVALS;
        j = tid - p * NVALS;
        const float* base = red + (p * SPP) * NVALS + j;
#pragma unroll
        for (int k = 0; k < SPP; k++) sum += base[k * NVALS];
        if (j == NBC) det_s[p] = sum;
    }
    __syncthreads();

    if (tid < PIX_PER_BLOCK * NVALS && j < NBC) {
        const int opix = blockIdx.x * PIX_PER_BLOCK + p;
        out[(size_t)j * (SH * SW) + opix] = sum / det_s[p];
    }
}

extern "C" void kernel_launch(void* const* d_in, const int* in_sizes, int n_in,
                              void* d_out, int out_size)
{
    const float* img    = (const float*)d_in[0];
    const float* t      = (const float*)d_in[1];
    const float* jitter = (const float*)d_in[2];
    float* out          = (float*)d_out;

    ffs_kernel<<<(SH * SW) / PIX_PER_BLOCK, BLOCK>>>(img, t, jitter, out);
}